// round 10
// baseline (speedup 1.0000x reference)
#include <cuda_runtime.h>
#include <math.h>

#define TLEN 32768
#define NF   65536
#define TWO_PI 6.283185307179586476925f

// 128 complex signals x 65536 points = 64 MB scratch.
// Layout between kernels: g_work[p][k1*4096 + n2]  (k1 = 0..15, n2 = 0..4095)
__device__ float2 g_work[128 * 65536];
// filter spectrum; after k_filt_rowB stored K2-register-matched:
// g_filt[k1*4096 + u2*256 + t]   (t = g*16 + l mapping)
__device__ float2 g_filt[65536];

__device__ __forceinline__ float2 cmul(float2 a, float2 b) {
    return make_float2(fmaf(a.x, b.x, -(a.y * b.y)), fmaf(a.x, b.y, a.y * b.x));
}

// packed f32x2 add/sub (Blackwell): 1 instruction for a complex add/sub
__device__ __forceinline__ float2 f2add(float2 a, float2 b) {
    float2 c;
    asm("{\n\t.reg .b64 ra, rb, rc;\n\t"
        "mov.b64 ra, {%2, %3};\n\t"
        "mov.b64 rb, {%4, %5};\n\t"
        "add.rn.f32x2 rc, ra, rb;\n\t"
        "mov.b64 {%0, %1}, rc;\n\t}"
        : "=f"(c.x), "=f"(c.y)
        : "f"(a.x), "f"(a.y), "f"(b.x), "f"(b.y));
    return c;
}
__device__ __forceinline__ float2 f2sub(float2 a, float2 b) {
    float2 c;
    asm("{\n\t.reg .b64 ra, rb, rc;\n\t"
        "mov.b64 ra, {%2, %3};\n\t"
        "mov.b64 rb, {%4, %5};\n\t"
        "sub.rn.f32x2 rc, ra, rb;\n\t"
        "mov.b64 {%0, %1}, rc;\n\t}"
        : "=f"(c.x), "=f"(c.y)
        : "f"(a.x), "f"(a.y), "f"(b.x), "f"(b.y));
    return c;
}

template<int SIGN>
__device__ __forceinline__ void fft4(float2& a0, float2& a1, float2& a2, float2& a3) {
    float2 s0 = f2add(a0, a2);
    float2 d0 = f2sub(a0, a2);
    float2 s1 = f2add(a1, a3);
    float2 d1 = f2sub(a1, a3);
    float2 wd1 = (SIGN < 0) ? make_float2(d1.y, -d1.x) : make_float2(-d1.y, d1.x);
    a0 = f2add(s0, s1);
    a2 = f2sub(s0, s1);
    a1 = f2add(d0, wd1);
    a3 = f2sub(d0, wd1);
}

template<int SIGN>
__device__ __forceinline__ float2 w16f(int m) {
    const float C[10] = {1.f, 0.92387953251128675613f, 0.70710678118654752440f,
                         0.38268343236508977173f, 0.f, -0.38268343236508977173f,
                         -0.70710678118654752440f, -0.92387953251128675613f,
                         -1.f, -0.92387953251128675613f};
    const float S[10] = {0.f, 0.38268343236508977173f, 0.70710678118654752440f,
                         0.92387953251128675613f, 1.f, 0.92387953251128675613f,
                         0.70710678118654752440f, 0.38268343236508977173f,
                         0.f, -0.38268343236508977173f};
    return make_float2(C[m], (SIGN < 0) ? -S[m] : S[m]);
}

// 16-point DFT, natural-order in/out
template<int SIGN>
__device__ __forceinline__ void fft16(float2 v[16]) {
    #pragma unroll
    for (int b = 0; b < 4; b++) fft4<SIGN>(v[b], v[4 + b], v[8 + b], v[12 + b]);
    #pragma unroll
    for (int p = 1; p < 4; p++) {
        #pragma unroll
        for (int b = 1; b < 4; b++)
            v[4 * p + b] = cmul(v[4 * p + b], w16f<SIGN>(b * p));
    }
    #pragma unroll
    for (int p = 0; p < 4; p++) fft4<SIGN>(v[4 * p + 0], v[4 * p + 1], v[4 * p + 2], v[4 * p + 3]);
    float2 o[16];
    #pragma unroll
    for (int q = 0; q < 4; q++)
        #pragma unroll
        for (int p = 0; p < 4; p++) o[4 * q + p] = v[4 * p + q];
    #pragma unroll
    for (int i = 0; i < 16; i++) v[i] = o[i];
}

// v[k] *= t0 * w^k for k = 0..15, via 4 independent chains of 4 (log depth).
__device__ __forceinline__ void twmul16(float2 v[16], float2 t0, float2 w) {
    float2 t2 = cmul(w, w);
    float2 t4 = cmul(t2, t2);
    float2 t8 = cmul(t4, t4);
    float2 a = t0;
    float2 b = cmul(t0, t4);
    float2 c = cmul(t0, t8);
    float2 d = cmul(b, t8);
    #pragma unroll
    for (int i = 0; i < 4; i++) {
        v[i]      = cmul(v[i], a);
        v[4 + i]  = cmul(v[4 + i], b);
        v[8 + i]  = cmul(v[8 + i], c);
        v[12 + i] = cmul(v[12 + i], d);
        if (i < 3) { a = cmul(a, w); b = cmul(b, w); c = cmul(c, w); d = cmul(d, w); }
    }
}

// 256-point DFT within one half-warp (group g = t>>4, lane l = t&15).
// Lane l holds v[j]=s[16j+l] on entry; on exit v[k2]=X[16*k2+l].
// Exchange is warp-private (group owns smem row g): __syncwarp only.
// XOR-rotation swizzle keeps both phases bank-conflict-free.
template<int SIGN>
__device__ __forceinline__ void fft256_core(float2 v[16], int l, int g,
                                            float2* sh) {
    fft16<SIGN>(v);
    float sv, cv;
    __sincosf(((SIGN < 0) ? -TWO_PI : TWO_PI) * (float)l / 256.0f, &sv, &cv);
    twmul16(v, make_float2(1.f, 0.f), make_float2(cv, sv));
    __syncwarp();
    #pragma unroll
    for (int k1 = 0; k1 < 16; k1++)
        sh[g * 257 + k1 * 16 + ((l + k1) & 15)] = v[k1];
    __syncwarp();
    #pragma unroll
    for (int n2 = 0; n2 < 16; n2++)
        v[n2] = sh[g * 257 + l * 16 + ((n2 + l) & 15)];
    fft16<SIGN>(v);
}

// ======== K1 (fused): stage A for signals (blocks 0..2047) and filter
// (blocks 2048..2063) — pure-register radix-16, no smem ========
__global__ void __launch_bounds__(256) k_colA(const float* __restrict__ x,
                                              const float* __restrict__ f) {
    int t = threadIdx.x;
    float2 v[16];
    if (blockIdx.x < 2048) {
        int p = blockIdx.x >> 4, blk = blockIdx.x & 15;
        int n2 = blk * 256 + t;
        const float* xr = x + (size_t)(2 * p) * TLEN;
        const float* xi = x + (size_t)(2 * p + 1) * TLEN;
        #pragma unroll
        for (int n1 = 0; n1 < 16; n1++) {
            if (n1 < 8) {  // n >= 32768 is zero padding
                int n = n1 * 4096 + n2;
                v[n1] = make_float2(xr[n], xi[n]);
            } else v[n1] = make_float2(0.f, 0.f);
        }
        fft16<-1>(v);  // over n1 -> v[k1]
        float s, c; __sincosf(-TWO_PI * (float)n2 / 65536.0f, &s, &c);
        twmul16(v, make_float2(1.f, 0.f), make_float2(c, s));
        float2* dst = g_work + (size_t)p * NF;
        #pragma unroll
        for (int k1 = 0; k1 < 16; k1++)
            dst[k1 * 4096 + n2] = v[k1];
    } else {
        int n2 = (blockIdx.x - 2048) * 256 + t;
        #pragma unroll
        for (int n1 = 0; n1 < 16; n1++) {
            if (n1 < 8) v[n1] = make_float2(f[n1 * 4096 + n2], 0.f);
            else v[n1] = make_float2(0.f, 0.f);
        }
        fft16<-1>(v);
        float s, c; __sincosf(-TWO_PI * (float)n2 / 65536.0f, &s, &c);
        twmul16(v, make_float2(1.f, 0.f), make_float2(c, s));
        #pragma unroll
        for (int k1 = 0; k1 < 16; k1++)
            g_filt[k1 * 4096 + n2] = v[k1];
    }
}

// ======== K0b: filter row-forward (4096-pt), writes K2-register-matched ========
__global__ void __launch_bounds__(256) k_filt_rowB() {
    __shared__ float2 sh[16 * 257];
    int t = threadIdx.x;
    int g = t >> 4, l = t & 15;   // half-warp = group
    int k1 = blockIdx.x;
    float2* base = g_filt + k1 * 4096;
    float2 v[16];
    #pragma unroll
    for (int a = 0; a < 16; a++) v[a] = base[a * 256 + t];
    fft16<-1>(v);  // over a -> v[t1] = F[t1][s=t]
    // T1 twiddle e^{-2pi i t * t1 / 4096}
    { float s_, c_; __sincosf(-TWO_PI * (float)t / 4096.0f, &s_, &c_);
      twmul16(v, make_float2(1.f, 0.f), make_float2(c_, s_)); }
    // RT1 transpose: group g takes row t1=g, elements s=16j+l
    #pragma unroll
    for (int t1 = 0; t1 < 16; t1++) sh[t1 * 257 + t] = v[t1];
    __syncthreads();
    #pragma unroll
    for (int j = 0; j < 16; j++) v[j] = sh[g * 257 + 16 * j + l];
    fft256_core<-1>(v, l, g, sh);
    // v[u2] = Wf[row g][16u2+l]; store K2-matched layout
    #pragma unroll
    for (int u2 = 0; u2 < 16; u2++) base[u2 * 256 + t] = v[u2];
}

// ======== K2: per-row 4096-pt FFT -> *Wf -> inverse (2 block barriers) ========
__global__ void __launch_bounds__(256, 4) k_rowB() {
    __shared__ float2 sh[16 * 257];
    int t = threadIdx.x;
    int g = t >> 4, l = t & 15;   // half-warp = group
    int p = blockIdx.x >> 4, k1 = blockIdx.x & 15;
    float2* base = g_work + (size_t)p * NF + k1 * 4096;
    const float2* __restrict__ wf = g_filt + k1 * 4096;
    float2 v[16];
    // forward stage 1: fft16 over a (stride 256), coalesced load
    #pragma unroll
    for (int a = 0; a < 16; a++) v[a] = base[a * 256 + t];
    fft16<-1>(v);  // -> v[t1] = F[t1][s=t]
    // T1 twiddle e^{-2pi i t * t1 / 4096}
    { float s_, c_; __sincosf(-TWO_PI * (float)t / 4096.0f, &s_, &c_);
      twmul16(v, make_float2(1.f, 0.f), make_float2(c_, s_)); }
    // RT1 transpose (block-wide)
    #pragma unroll
    for (int t1 = 0; t1 < 16; t1++) sh[t1 * 257 + t] = v[t1];
    __syncthreads();
    #pragma unroll
    for (int j = 0; j < 16; j++) v[j] = sh[g * 257 + 16 * j + l];
    // forward stage 2+3: 256-pt FFT over s for row t1=g (warp-private)
    fft256_core<-1>(v, l, g, sh);
    // pointwise multiply (register-coalesced; wf layout matches exactly)
    #pragma unroll
    for (int u2 = 0; u2 < 16; u2++)
        v[u2] = cmul(v[u2], wf[u2 * 256 + t]);
    // inverse stage 3+2 (warp-private)
    fft256_core<1>(v, l, g, sh);
    // undo T1: e^{+2pi i s*g/4096}, s = 16*sg + l, row g
    { float s_, c_; __sincosf(TWO_PI * (float)(l * g) / 4096.0f, &s_, &c_);
      float ss, cs; __sincosf(TWO_PI * (float)g / 256.0f, &ss, &cs);
      twmul16(v, make_float2(c_, s_), make_float2(cs, ss)); }
    // RT4 transpose back (block-wide): thread t gets all t1 for s=t
    __syncwarp();
    #pragma unroll
    for (int sg = 0; sg < 16; sg++) sh[g * 257 + 16 * sg + l] = v[sg];
    __syncthreads();
    #pragma unroll
    for (int t1 = 0; t1 < 16; t1++) v[t1] = sh[t1 * 257 + t];
    // inverse stage 1: fft16 over t1 -> v[a] = z'[256a + t]; store directly
    fft16<1>(v);
    #pragma unroll
    for (int a = 0; a < 16; a++)
        base[a * 256 + t] = v[a];
}

// ======== K3: conj twiddle + inverse stage A (16-pt over k1) + scale + y ========
__global__ void __launch_bounds__(256) k_colA_inv(float* __restrict__ y) {
    int t = threadIdx.x;
    int p = blockIdx.x >> 4, blk = blockIdx.x & 15;
    int n2 = blk * 256 + t;
    const float2* src = g_work + (size_t)p * NF;
    float2 v[16];
    #pragma unroll
    for (int k1 = 0; k1 < 16; k1++)
        v[k1] = src[k1 * 4096 + n2];
    // conj inter-stage twiddle e^{+2pi i n2 k1 / 65536}
    { float s, c; __sincosf(TWO_PI * (float)n2 / 65536.0f, &s, &c);
      twmul16(v, make_float2(1.f, 0.f), make_float2(c, s)); }
    fft16<1>(v);  // over k1 -> v[n1]
    const float inv = 1.0f / 65536.0f;
    float* yr = y + (size_t)(2 * p) * TLEN;
    float* yi = y + (size_t)(2 * p + 1) * TLEN;
    #pragma unroll
    for (int n1 = 0; n1 < 8; n1++) {  // only n < T
        int n = n1 * 4096 + n2;
        yr[n] = v[n1].x * inv;
        yi[n] = v[n1].y * inv;
    }
}

extern "C" void kernel_launch(void* const* d_in, const int* in_sizes, int n_in,
                              void* d_out, int out_size) {
    const float* x = (const float*)d_in[0];
    const float* f = (const float*)d_in[1];
    float* y = (float*)d_out;

    k_colA<<<2064, 256>>>(x, f);    // signals + filter stage A (fused)
    k_filt_rowB<<<16, 256>>>();     // filter: 4096-pt row fwd -> K2 layout
    k_rowB<<<2048, 256>>>();        // 4096 fwd, *Wf, 4096 inv (2 barriers)
    k_colA_inv<<<2048, 256>>>(y);   // conj twiddle + stage A inverse + scale
}

// round 11
// speedup vs baseline: 1.0407x; 1.0407x over previous
#include <cuda_runtime.h>
#include <math.h>

#define TLEN 32768
#define NF   65536
#define TWO_PI 6.283185307179586476925f

// 128 complex signals x 65536 points = 64 MB scratch.
// Layout between kernels: g_work[p][k1*4096 + n2]  (k1 = 0..15, n2 = 0..4095)
__device__ float2 g_work[128 * 65536];
// filter spectrum; after k_filt_rowB stored K2-register-matched:
// g_filt[k1*4096 + u2*256 + t]   (t = g*16 + l mapping)
__device__ float2 g_filt[65536];

__device__ __forceinline__ float2 cmul(float2 a, float2 b) {
    return make_float2(fmaf(a.x, b.x, -(a.y * b.y)), fmaf(a.x, b.y, a.y * b.x));
}

// packed f32x2 add/sub (Blackwell): 1 instruction for a complex add/sub
__device__ __forceinline__ float2 f2add(float2 a, float2 b) {
    float2 c;
    asm("{\n\t.reg .b64 ra, rb, rc;\n\t"
        "mov.b64 ra, {%2, %3};\n\t"
        "mov.b64 rb, {%4, %5};\n\t"
        "add.rn.f32x2 rc, ra, rb;\n\t"
        "mov.b64 {%0, %1}, rc;\n\t}"
        : "=f"(c.x), "=f"(c.y)
        : "f"(a.x), "f"(a.y), "f"(b.x), "f"(b.y));
    return c;
}
__device__ __forceinline__ float2 f2sub(float2 a, float2 b) {
    float2 c;
    asm("{\n\t.reg .b64 ra, rb, rc;\n\t"
        "mov.b64 ra, {%2, %3};\n\t"
        "mov.b64 rb, {%4, %5};\n\t"
        "sub.rn.f32x2 rc, ra, rb;\n\t"
        "mov.b64 {%0, %1}, rc;\n\t}"
        : "=f"(c.x), "=f"(c.y)
        : "f"(a.x), "f"(a.y), "f"(b.x), "f"(b.y));
    return c;
}

template<int SIGN>
__device__ __forceinline__ void fft4(float2& a0, float2& a1, float2& a2, float2& a3) {
    float2 s0 = f2add(a0, a2);
    float2 d0 = f2sub(a0, a2);
    float2 s1 = f2add(a1, a3);
    float2 d1 = f2sub(a1, a3);
    float2 wd1 = (SIGN < 0) ? make_float2(d1.y, -d1.x) : make_float2(-d1.y, d1.x);
    a0 = f2add(s0, s1);
    a2 = f2sub(s0, s1);
    a1 = f2add(d0, wd1);
    a3 = f2sub(d0, wd1);
}

template<int SIGN>
__device__ __forceinline__ float2 w16f(int m) {
    const float C[10] = {1.f, 0.92387953251128675613f, 0.70710678118654752440f,
                         0.38268343236508977173f, 0.f, -0.38268343236508977173f,
                         -0.70710678118654752440f, -0.92387953251128675613f,
                         -1.f, -0.92387953251128675613f};
    const float S[10] = {0.f, 0.38268343236508977173f, 0.70710678118654752440f,
                         0.92387953251128675613f, 1.f, 0.92387953251128675613f,
                         0.70710678118654752440f, 0.38268343236508977173f,
                         0.f, -0.38268343236508977173f};
    return make_float2(C[m], (SIGN < 0) ? -S[m] : S[m]);
}

// 16-point DFT, natural-order in/out
template<int SIGN>
__device__ __forceinline__ void fft16(float2 v[16]) {
    #pragma unroll
    for (int b = 0; b < 4; b++) fft4<SIGN>(v[b], v[4 + b], v[8 + b], v[12 + b]);
    #pragma unroll
    for (int p = 1; p < 4; p++) {
        #pragma unroll
        for (int b = 1; b < 4; b++)
            v[4 * p + b] = cmul(v[4 * p + b], w16f<SIGN>(b * p));
    }
    #pragma unroll
    for (int p = 0; p < 4; p++) fft4<SIGN>(v[4 * p + 0], v[4 * p + 1], v[4 * p + 2], v[4 * p + 3]);
    float2 o[16];
    #pragma unroll
    for (int q = 0; q < 4; q++)
        #pragma unroll
        for (int p = 0; p < 4; p++) o[4 * q + p] = v[4 * p + q];
    #pragma unroll
    for (int i = 0; i < 16; i++) v[i] = o[i];
}

// v[k] *= t0 * w^k for k = 0..15, via 4 independent chains of 4 (log depth).
__device__ __forceinline__ void twmul16(float2 v[16], float2 t0, float2 w) {
    float2 t2 = cmul(w, w);
    float2 t4 = cmul(t2, t2);
    float2 t8 = cmul(t4, t4);
    float2 a = t0;
    float2 b = cmul(t0, t4);
    float2 c = cmul(t0, t8);
    float2 d = cmul(b, t8);
    #pragma unroll
    for (int i = 0; i < 4; i++) {
        v[i]      = cmul(v[i], a);
        v[4 + i]  = cmul(v[4 + i], b);
        v[8 + i]  = cmul(v[8 + i], c);
        v[12 + i] = cmul(v[12 + i], d);
        if (i < 3) { a = cmul(a, w); b = cmul(b, w); c = cmul(c, w); d = cmul(d, w); }
    }
}

// 256-point DFT within one half-warp (group g = t>>4, lane l = t&15).
// Lane l holds v[j]=s[16j+l] on entry; on exit v[k2]=X[16*k2+l].
// Warp-private exchange via pad-17 row (272 float2/group): write k1*17+l,
// read l*17+n2 — both phases bank-conflict-free with zero address ALU.
template<int SIGN>
__device__ __forceinline__ void fft256_core(float2 v[16], int l, int g,
                                            float2* sh) {
    fft16<SIGN>(v);
    float sv, cv;
    __sincosf(((SIGN < 0) ? -TWO_PI : TWO_PI) * (float)l / 256.0f, &sv, &cv);
    twmul16(v, make_float2(1.f, 0.f), make_float2(cv, sv));
    __syncwarp();
    #pragma unroll
    for (int k1 = 0; k1 < 16; k1++)
        sh[g * 272 + k1 * 17 + l] = v[k1];
    __syncwarp();
    #pragma unroll
    for (int n2 = 0; n2 < 16; n2++)
        v[n2] = sh[g * 272 + l * 17 + n2];
    fft16<SIGN>(v);
}

// ======== K1 (fused): stage A for signals (blocks 0..2047) and filter
// (blocks 2048..2063) — pure-register radix-16, no smem ========
__global__ void __launch_bounds__(256) k_colA(const float* __restrict__ x,
                                              const float* __restrict__ f) {
    int t = threadIdx.x;
    float2 v[16];
    if (blockIdx.x < 2048) {
        int p = blockIdx.x >> 4, blk = blockIdx.x & 15;
        int n2 = blk * 256 + t;
        const float* xr = x + (size_t)(2 * p) * TLEN;
        const float* xi = x + (size_t)(2 * p + 1) * TLEN;
        #pragma unroll
        for (int n1 = 0; n1 < 16; n1++) {
            if (n1 < 8) {  // n >= 32768 is zero padding
                int n = n1 * 4096 + n2;
                v[n1] = make_float2(xr[n], xi[n]);
            } else v[n1] = make_float2(0.f, 0.f);
        }
        fft16<-1>(v);  // over n1 -> v[k1]
        float s, c; __sincosf(-TWO_PI * (float)n2 / 65536.0f, &s, &c);
        twmul16(v, make_float2(1.f, 0.f), make_float2(c, s));
        float2* dst = g_work + (size_t)p * NF;
        #pragma unroll
        for (int k1 = 0; k1 < 16; k1++)
            dst[k1 * 4096 + n2] = v[k1];
    } else {
        int n2 = (blockIdx.x - 2048) * 256 + t;
        #pragma unroll
        for (int n1 = 0; n1 < 16; n1++) {
            if (n1 < 8) v[n1] = make_float2(f[n1 * 4096 + n2], 0.f);
            else v[n1] = make_float2(0.f, 0.f);
        }
        fft16<-1>(v);
        float s, c; __sincosf(-TWO_PI * (float)n2 / 65536.0f, &s, &c);
        twmul16(v, make_float2(1.f, 0.f), make_float2(c, s));
        #pragma unroll
        for (int k1 = 0; k1 < 16; k1++)
            g_filt[k1 * 4096 + n2] = v[k1];
    }
}

// ======== K0b: filter row-forward (4096-pt), writes K2-register-matched ========
__global__ void __launch_bounds__(256) k_filt_rowB() {
    __shared__ float2 sh[16 * 272];
    int t = threadIdx.x;
    int g = t >> 4, l = t & 15;   // half-warp = group
    int k1 = blockIdx.x;
    float2* base = g_filt + k1 * 4096;
    float2 v[16];
    #pragma unroll
    for (int a = 0; a < 16; a++) v[a] = base[a * 256 + t];
    fft16<-1>(v);  // over a -> v[t1] = F[t1][s=t]
    // T1 twiddle e^{-2pi i t * t1 / 4096}
    { float s_, c_; __sincosf(-TWO_PI * (float)t / 4096.0f, &s_, &c_);
      twmul16(v, make_float2(1.f, 0.f), make_float2(c_, s_)); }
    // RT1 transpose: group g takes row t1=g, elements s=16j+l
    #pragma unroll
    for (int t1 = 0; t1 < 16; t1++) sh[t1 * 272 + t] = v[t1];
    __syncthreads();
    #pragma unroll
    for (int j = 0; j < 16; j++) v[j] = sh[g * 272 + 16 * j + l];
    fft256_core<-1>(v, l, g, sh);
    // v[u2] = Wf[row g][16u2+l]; store K2-matched layout
    #pragma unroll
    for (int u2 = 0; u2 < 16; u2++) base[u2 * 256 + t] = v[u2];
}

// ======== K2: per-row 4096-pt FFT -> *Wf -> inverse (2 block barriers) ========
__global__ void __launch_bounds__(256, 4) k_rowB() {
    __shared__ float2 sh[16 * 272];
    int t = threadIdx.x;
    int g = t >> 4, l = t & 15;   // half-warp = group
    int p = blockIdx.x >> 4, k1 = blockIdx.x & 15;
    float2* base = g_work + (size_t)p * NF + k1 * 4096;
    const float2* __restrict__ wf = g_filt + k1 * 4096;
    float2 v[16];
    // forward stage 1: fft16 over a (stride 256), coalesced load
    #pragma unroll
    for (int a = 0; a < 16; a++) v[a] = base[a * 256 + t];
    fft16<-1>(v);  // -> v[t1] = F[t1][s=t]
    // T1 twiddle e^{-2pi i t * t1 / 4096}
    { float s_, c_; __sincosf(-TWO_PI * (float)t / 4096.0f, &s_, &c_);
      twmul16(v, make_float2(1.f, 0.f), make_float2(c_, s_)); }
    // RT1 transpose (block-wide)
    #pragma unroll
    for (int t1 = 0; t1 < 16; t1++) sh[t1 * 272 + t] = v[t1];
    __syncthreads();
    #pragma unroll
    for (int j = 0; j < 16; j++) v[j] = sh[g * 272 + 16 * j + l];
    // forward stage 2+3: 256-pt FFT over s for row t1=g (warp-private)
    fft256_core<-1>(v, l, g, sh);
    // pointwise multiply (register-coalesced; wf layout matches exactly)
    #pragma unroll
    for (int u2 = 0; u2 < 16; u2++)
        v[u2] = cmul(v[u2], wf[u2 * 256 + t]);
    // inverse stage 3+2 (warp-private)
    fft256_core<1>(v, l, g, sh);
    // undo T1: e^{+2pi i s*g/4096}, s = 16*sg + l, row g
    { float s_, c_; __sincosf(TWO_PI * (float)(l * g) / 4096.0f, &s_, &c_);
      float ss, cs; __sincosf(TWO_PI * (float)g / 256.0f, &ss, &cs);
      twmul16(v, make_float2(c_, s_), make_float2(cs, ss)); }
    // RT4 transpose back (block-wide): thread t gets all t1 for s=t
    __syncwarp();
    #pragma unroll
    for (int sg = 0; sg < 16; sg++) sh[g * 272 + 16 * sg + l] = v[sg];
    __syncthreads();
    #pragma unroll
    for (int t1 = 0; t1 < 16; t1++) v[t1] = sh[t1 * 272 + t];
    // inverse stage 1: fft16 over t1 -> v[a] = z'[256a + t]; store directly
    fft16<1>(v);
    #pragma unroll
    for (int a = 0; a < 16; a++)
        base[a * 256 + t] = v[a];
}

// ======== K3: conj twiddle + inverse stage A (16-pt over k1) + scale + y ========
__global__ void __launch_bounds__(256) k_colA_inv(float* __restrict__ y) {
    int t = threadIdx.x;
    int p = blockIdx.x >> 4, blk = blockIdx.x & 15;
    int n2 = blk * 256 + t;
    const float2* src = g_work + (size_t)p * NF;
    float2 v[16];
    #pragma unroll
    for (int k1 = 0; k1 < 16; k1++)
        v[k1] = src[k1 * 4096 + n2];
    // conj inter-stage twiddle e^{+2pi i n2 k1 / 65536}
    { float s, c; __sincosf(TWO_PI * (float)n2 / 65536.0f, &s, &c);
      twmul16(v, make_float2(1.f, 0.f), make_float2(c, s)); }
    fft16<1>(v);  // over k1 -> v[n1]
    const float inv = 1.0f / 65536.0f;
    float* yr = y + (size_t)(2 * p) * TLEN;
    float* yi = y + (size_t)(2 * p + 1) * TLEN;
    #pragma unroll
    for (int n1 = 0; n1 < 8; n1++) {  // only n < T
        int n = n1 * 4096 + n2;
        yr[n] = v[n1].x * inv;
        yi[n] = v[n1].y * inv;
    }
}

extern "C" void kernel_launch(void* const* d_in, const int* in_sizes, int n_in,
                              void* d_out, int out_size) {
    const float* x = (const float*)d_in[0];
    const float* f = (const float*)d_in[1];
    float* y = (float*)d_out;

    k_colA<<<2064, 256>>>(x, f);    // signals + filter stage A (fused)
    k_filt_rowB<<<16, 256>>>();     // filter: 4096-pt row fwd -> K2 layout
    k_rowB<<<2048, 256>>>();        // 4096 fwd, *Wf, 4096 inv (2 barriers)
    k_colA_inv<<<2048, 256>>>(y);   // conj twiddle + stage A inverse + scale
}

// round 12
// speedup vs baseline: 1.2622x; 1.2129x over previous
#include <cuda_runtime.h>
#include <cuda_fp16.h>
#include <math.h>

#define TLEN 32768
#define NF   65536
#define TWO_PI 6.283185307179586476925f

// 128 complex signals x 65536 points, fp16 (re,im) packed = 32 MB scratch.
// Layout between kernels: g_work[p][k1*4096 + n2]
__device__ __half2 g_work[128 * 65536];
// filter spectrum (fp32); after k_filt_rowB stored K2-register-matched AND
// scaled by 1/65536: g_filt[k1*4096 + u2*256 + t]
__device__ float2 g_filt[65536];

__device__ __forceinline__ float2 cmul(float2 a, float2 b) {
    return make_float2(fmaf(a.x, b.x, -(a.y * b.y)), fmaf(a.x, b.y, a.y * b.x));
}
__device__ __forceinline__ __half2 pack_h2(float2 a) { return __floats2half2_rn(a.x, a.y); }
__device__ __forceinline__ float2 unpack_h2(__half2 h) {
    float2 f = __half22float2(h);
    return make_float2(f.x, f.y);
}

// packed f32x2 add/sub (Blackwell): 1 instruction for a complex add/sub
__device__ __forceinline__ float2 f2add(float2 a, float2 b) {
    float2 c;
    asm("{\n\t.reg .b64 ra, rb, rc;\n\t"
        "mov.b64 ra, {%2, %3};\n\t"
        "mov.b64 rb, {%4, %5};\n\t"
        "add.rn.f32x2 rc, ra, rb;\n\t"
        "mov.b64 {%0, %1}, rc;\n\t}"
        : "=f"(c.x), "=f"(c.y)
        : "f"(a.x), "f"(a.y), "f"(b.x), "f"(b.y));
    return c;
}
__device__ __forceinline__ float2 f2sub(float2 a, float2 b) {
    float2 c;
    asm("{\n\t.reg .b64 ra, rb, rc;\n\t"
        "mov.b64 ra, {%2, %3};\n\t"
        "mov.b64 rb, {%4, %5};\n\t"
        "sub.rn.f32x2 rc, ra, rb;\n\t"
        "mov.b64 {%0, %1}, rc;\n\t}"
        : "=f"(c.x), "=f"(c.y)
        : "f"(a.x), "f"(a.y), "f"(b.x), "f"(b.y));
    return c;
}

template<int SIGN>
__device__ __forceinline__ void fft4(float2& a0, float2& a1, float2& a2, float2& a3) {
    float2 s0 = f2add(a0, a2);
    float2 d0 = f2sub(a0, a2);
    float2 s1 = f2add(a1, a3);
    float2 d1 = f2sub(a1, a3);
    float2 wd1 = (SIGN < 0) ? make_float2(d1.y, -d1.x) : make_float2(-d1.y, d1.x);
    a0 = f2add(s0, s1);
    a2 = f2sub(s0, s1);
    a1 = f2add(d0, wd1);
    a3 = f2sub(d0, wd1);
}

template<int SIGN>
__device__ __forceinline__ float2 w16f(int m) {
    const float C[10] = {1.f, 0.92387953251128675613f, 0.70710678118654752440f,
                         0.38268343236508977173f, 0.f, -0.38268343236508977173f,
                         -0.70710678118654752440f, -0.92387953251128675613f,
                         -1.f, -0.92387953251128675613f};
    const float S[10] = {0.f, 0.38268343236508977173f, 0.70710678118654752440f,
                         0.92387953251128675613f, 1.f, 0.92387953251128675613f,
                         0.70710678118654752440f, 0.38268343236508977173f,
                         0.f, -0.38268343236508977173f};
    return make_float2(C[m], (SIGN < 0) ? -S[m] : S[m]);
}

// 16-point DFT, natural-order in/out
template<int SIGN>
__device__ __forceinline__ void fft16(float2 v[16]) {
    #pragma unroll
    for (int b = 0; b < 4; b++) fft4<SIGN>(v[b], v[4 + b], v[8 + b], v[12 + b]);
    #pragma unroll
    for (int p = 1; p < 4; p++) {
        #pragma unroll
        for (int b = 1; b < 4; b++)
            v[4 * p + b] = cmul(v[4 * p + b], w16f<SIGN>(b * p));
    }
    #pragma unroll
    for (int p = 0; p < 4; p++) fft4<SIGN>(v[4 * p + 0], v[4 * p + 1], v[4 * p + 2], v[4 * p + 3]);
    float2 o[16];
    #pragma unroll
    for (int q = 0; q < 4; q++)
        #pragma unroll
        for (int p = 0; p < 4; p++) o[4 * q + p] = v[4 * p + q];
    #pragma unroll
    for (int i = 0; i < 16; i++) v[i] = o[i];
}

// v[k] *= t0 * w^k for k = 0..15, via 4 independent chains of 4 (log depth).
__device__ __forceinline__ void twmul16(float2 v[16], float2 t0, float2 w) {
    float2 t2 = cmul(w, w);
    float2 t4 = cmul(t2, t2);
    float2 t8 = cmul(t4, t4);
    float2 a = t0;
    float2 b = cmul(t0, t4);
    float2 c = cmul(t0, t8);
    float2 d = cmul(b, t8);
    #pragma unroll
    for (int i = 0; i < 4; i++) {
        v[i]      = cmul(v[i], a);
        v[4 + i]  = cmul(v[4 + i], b);
        v[8 + i]  = cmul(v[8 + i], c);
        v[12 + i] = cmul(v[12 + i], d);
        if (i < 3) { a = cmul(a, w); b = cmul(b, w); c = cmul(c, w); d = cmul(d, w); }
    }
}

// 256-point DFT across 16 lanes (lane l holds v[j]=s[16j+l] on entry;
// on exit lane l holds v[k2]=X[16*k2+l]). Exchange via shared row g. (R9 config)
template<int SIGN>
__device__ __forceinline__ void fft256_core(float2 v[16], int l, int g,
                                            float2* sh) {
    fft16<SIGN>(v);
    float sv, cv;
    __sincosf(((SIGN < 0) ? -TWO_PI : TWO_PI) * (float)l / 256.0f, &sv, &cv);
    twmul16(v, make_float2(1.f, 0.f), make_float2(cv, sv));
    __syncthreads();
    #pragma unroll
    for (int k1 = 0; k1 < 16; k1++)
        sh[g * 257 + k1 * 16 + l] = v[k1];
    __syncthreads();
    #pragma unroll
    for (int n2 = 0; n2 < 16; n2++)
        v[n2] = sh[g * 257 + l * 16 + n2];
    fft16<SIGN>(v);
}

// ======== K1 (fused): stage A for signals (blocks 0..2047, half2 out) and
// filter (blocks 2048..2063, float2 out) — pure-register radix-16 ========
__global__ void __launch_bounds__(256) k_colA(const float* __restrict__ x,
                                              const float* __restrict__ f) {
    int t = threadIdx.x;
    float2 v[16];
    if (blockIdx.x < 2048) {
        int p = blockIdx.x >> 4, blk = blockIdx.x & 15;
        int n2 = blk * 256 + t;
        const float* xr = x + (size_t)(2 * p) * TLEN;
        const float* xi = x + (size_t)(2 * p + 1) * TLEN;
        #pragma unroll
        for (int n1 = 0; n1 < 16; n1++) {
            if (n1 < 8) {  // n >= 32768 is zero padding
                int n = n1 * 4096 + n2;
                v[n1] = make_float2(xr[n], xi[n]);
            } else v[n1] = make_float2(0.f, 0.f);
        }
        fft16<-1>(v);  // over n1 -> v[k1]
        float s, c; __sincosf(-TWO_PI * (float)n2 / 65536.0f, &s, &c);
        twmul16(v, make_float2(1.f, 0.f), make_float2(c, s));
        __half2* dst = g_work + (size_t)p * NF;
        #pragma unroll
        for (int k1 = 0; k1 < 16; k1++)
            dst[k1 * 4096 + n2] = pack_h2(v[k1]);
    } else {
        int n2 = (blockIdx.x - 2048) * 256 + t;
        #pragma unroll
        for (int n1 = 0; n1 < 16; n1++) {
            if (n1 < 8) v[n1] = make_float2(f[n1 * 4096 + n2], 0.f);
            else v[n1] = make_float2(0.f, 0.f);
        }
        fft16<-1>(v);
        float s, c; __sincosf(-TWO_PI * (float)n2 / 65536.0f, &s, &c);
        twmul16(v, make_float2(1.f, 0.f), make_float2(c, s));
        #pragma unroll
        for (int k1 = 0; k1 < 16; k1++)
            g_filt[k1 * 4096 + n2] = v[k1];
    }
}

// ======== K0b: filter row-forward (4096-pt), K2-matched layout, 1/65536 fold ===
__global__ void __launch_bounds__(256) k_filt_rowB() {
    __shared__ float2 sh[16 * 257];
    int t = threadIdx.x;
    int l = t >> 4, g = t & 15;
    int k1 = blockIdx.x;
    float2* base = g_filt + k1 * 4096;
    float2 v[16];
    #pragma unroll
    for (int a = 0; a < 16; a++) v[a] = base[a * 256 + t];
    fft16<-1>(v);  // over a -> v[t1] = F[t1][s=t]
    // T1 twiddle e^{-2pi i t * t1 / 4096}
    { float s_, c_; __sincosf(-TWO_PI * (float)t / 4096.0f, &s_, &c_);
      twmul16(v, make_float2(1.f, 0.f), make_float2(c_, s_)); }
    // RT1 transpose: thread (l,g) gets row t1=g, elements s=16j+l
    #pragma unroll
    for (int t1 = 0; t1 < 16; t1++) sh[t1 * 257 + t] = v[t1];
    __syncthreads();
    #pragma unroll
    for (int j = 0; j < 16; j++) v[j] = sh[g * 257 + 16 * j + l];
    fft256_core<-1>(v, l, g, sh);
    // store K2-matched layout, folding the FFT normalization 1/65536
    const float inv = 1.0f / 65536.0f;
    #pragma unroll
    for (int u2 = 0; u2 < 16; u2++) {
        float2 r = v[u2];
        base[u2 * 256 + t] = make_float2(r.x * inv, r.y * inv);
    }
}

// ======== K2: per-row 4096-pt FFT -> *Wf -> inverse (half2 in/out) ========
__global__ void __launch_bounds__(256, 4) k_rowB() {
    __shared__ float2 sh[16 * 257];
    int t = threadIdx.x;
    int l = t >> 4, g = t & 15;
    int p = blockIdx.x >> 4, k1 = blockIdx.x & 15;
    __half2* base = g_work + (size_t)p * NF + k1 * 4096;
    const float2* __restrict__ wf = g_filt + k1 * 4096;
    float2 v[16];
    // forward stage 1: fft16 over a (stride 256), coalesced half2 load
    #pragma unroll
    for (int a = 0; a < 16; a++) v[a] = unpack_h2(base[a * 256 + t]);
    fft16<-1>(v);  // -> v[t1] = F[t1][s=t]
    // T1 twiddle e^{-2pi i t * t1 / 4096}
    { float s_, c_; __sincosf(-TWO_PI * (float)t / 4096.0f, &s_, &c_);
      twmul16(v, make_float2(1.f, 0.f), make_float2(c_, s_)); }
    // RT1 transpose (block-wide)
    #pragma unroll
    for (int t1 = 0; t1 < 16; t1++) sh[t1 * 257 + t] = v[t1];
    __syncthreads();
    #pragma unroll
    for (int j = 0; j < 16; j++) v[j] = sh[g * 257 + 16 * j + l];
    // forward stage 2+3: 256-pt FFT over s for row t1=g
    fft256_core<-1>(v, l, g, sh);
    // pointwise multiply (register-coalesced; wf layout matches, incl. 1/65536)
    #pragma unroll
    for (int u2 = 0; u2 < 16; u2++)
        v[u2] = cmul(v[u2], wf[u2 * 256 + t]);
    // inverse stage 3+2: 256-pt inverse over u
    fft256_core<1>(v, l, g, sh);
    // undo T1: e^{+2pi i s*g/4096}, s = 16*sigma + l
    { float s_, c_; __sincosf(TWO_PI * (float)(l * g) / 4096.0f, &s_, &c_);
      float ss, cs; __sincosf(TWO_PI * (float)g / 256.0f, &ss, &cs);
      twmul16(v, make_float2(c_, s_), make_float2(cs, ss)); }
    // RT4 transpose back (block-wide): thread t gets all t1 for s=t
    __syncthreads();
    #pragma unroll
    for (int sg = 0; sg < 16; sg++) sh[g * 257 + 16 * sg + l] = v[sg];
    __syncthreads();
    #pragma unroll
    for (int t1 = 0; t1 < 16; t1++) v[t1] = sh[t1 * 257 + t];
    // inverse stage 1: fft16 over t1 -> v[a] = z'[256a + t]; half2 store
    fft16<1>(v);
    #pragma unroll
    for (int a = 0; a < 16; a++)
        base[a * 256 + t] = pack_h2(v[a]);
}

// ======== K3: conj twiddle + inverse stage A (16-pt over k1) + write y ========
// (1/65536 already folded into the filter spectrum)
__global__ void __launch_bounds__(256) k_colA_inv(float* __restrict__ y) {
    int t = threadIdx.x;
    int p = blockIdx.x >> 4, blk = blockIdx.x & 15;
    int n2 = blk * 256 + t;
    const __half2* src = g_work + (size_t)p * NF;
    float2 v[16];
    #pragma unroll
    for (int k1 = 0; k1 < 16; k1++)
        v[k1] = unpack_h2(src[k1 * 4096 + n2]);
    // conj inter-stage twiddle e^{+2pi i n2 k1 / 65536}
    { float s, c; __sincosf(TWO_PI * (float)n2 / 65536.0f, &s, &c);
      twmul16(v, make_float2(1.f, 0.f), make_float2(c, s)); }
    fft16<1>(v);  // over k1 -> v[n1]
    float* yr = y + (size_t)(2 * p) * TLEN;
    float* yi = y + (size_t)(2 * p + 1) * TLEN;
    #pragma unroll
    for (int n1 = 0; n1 < 8; n1++) {  // only n < T
        int n = n1 * 4096 + n2;
        yr[n] = v[n1].x;
        yi[n] = v[n1].y;
    }
}

extern "C" void kernel_launch(void* const* d_in, const int* in_sizes, int n_in,
                              void* d_out, int out_size) {
    const float* x = (const float*)d_in[0];
    const float* f = (const float*)d_in[1];
    float* y = (float*)d_out;

    k_colA<<<2064, 256>>>(x, f);    // signals (half2 out) + filter stage A
    k_filt_rowB<<<16, 256>>>();     // filter: row fwd -> K2 layout (×1/65536)
    k_rowB<<<2048, 256>>>();        // 4096 fwd, *Wf, 4096 inv (half2 I/O)
    k_colA_inv<<<2048, 256>>>(y);   // conj twiddle + stage A inverse
}